// round 11
// baseline (speedup 1.0000x reference)
#include <cuda_runtime.h>
#include <cuda_fp16.h>
#include <cstdint>

#define OBSD 128
#define ACTD 32
#define HIDD 256
#define NP   64
#define NB   4096
#define MT   128              // per CTA (two 64-row warpgroups)
#define EPSV 1e-5f

// ---------------- SMEM layout (bytes) ----------------
// per-WG A frags: wg*32768 ; params: 65536 + wg*6144 (two 3072B buffers)
// red: 77824 + wg*4096 (red1 2048B, red2 2048B) ; flag: 86016
#define A_OFF(wg)    ((wg) * 32768)
#define PAR_OFF(wg)  (65536 + (wg) * 6144)
#define RED_OFF(wg)  (77824 + (wg) * 4096)
#define FLAG_OFF     86016
#define DSMEM_BYTES  86144

// ---------------- weight fragment image ----------------
#define L1_BYTES ((size_t)OBSD*HIDD*4)   // per-policy bytes (hi+lo fp16 = 4B/elem)
#define L2_BYTES ((size_t)HIDD*HIDD*4)
#define L4_BYTES ((size_t)HIDD*ACTD*4)
#define OFF_L1 0ull
#define OFF_L2 (OFF_L1 + 64ull*L1_BYTES)
#define OFF_L3 (OFF_L2 + 64ull*L2_BYTES)
#define OFF_L4 (OFF_L3 + 64ull*L2_BYTES)
#define WIMG_TOTAL (OFF_L4 + 64ull*L4_BYTES)

__device__ __align__(128) unsigned char g_wimg[WIMG_TOTAL];

// ---------------- helpers ----------------
#define BARWG(id) asm volatile("bar.sync %0, 256;" :: "r"(id) : "memory")

__device__ __forceinline__ void mma16816(float* c, const uint4& a, uint32_t b0, uint32_t b1) {
    asm volatile(
        "mma.sync.aligned.m16n8k16.row.col.f32.f16.f16.f32 "
        "{%0,%1,%2,%3}, {%4,%5,%6,%7}, {%8,%9}, {%0,%1,%2,%3};"
        : "+f"(c[0]), "+f"(c[1]), "+f"(c[2]), "+f"(c[3])
        : "r"(a.x), "r"(a.y), "r"(a.z), "r"(a.w), "r"(b0), "r"(b1));
}

__device__ __forceinline__ uint32_t pack_f16(float y0, float y1) {
    uint32_t r;
    asm("cvt.rn.f16x2.f32 %0, %2, %1;" : "=r"(r) : "f"(y0), "f"(y1));
    return r;
}

__device__ __forceinline__ void split_pack_f16(float y0, float y1, uint32_t& hp, uint32_t& lp) {
    hp = pack_f16(y0, y1);
    float f0 = __half2float(__ushort_as_half((unsigned short)(hp & 0xffffu)));
    float f1 = __half2float(__ushort_as_half((unsigned short)(hp >> 16)));
    lp = pack_f16(y0 - f0, y1 - f1);
}

__device__ __forceinline__ float elu1(float y) { return y > 0.f ? y : (__expf(y) - 1.f); }

// ---------------- weight preprocess (merged, validated) ----------------
template<int N, int K>
__device__ __forceinline__ void prep_dev(const float* __restrict__ W, size_t off, float* tile)
{
    const int p = blockIdx.x, kt = blockIdx.y;
    if (kt >= K / 16) return;
    const int tid = threadIdx.x;
    const float4* src = reinterpret_cast<const float4*>(W + ((size_t)p * K + (size_t)kt * 16) * N);
    constexpr int NL4 = 16 * N / 4;
    for (int i = tid; i < NL4; i += 256)
        reinterpret_cast<float4*>(tile)[i] = src[i];
    __syncthreads();
    constexpr int NT = N / 8;
    uint4* dst = reinterpret_cast<uint4*>(g_wimg + off + (size_t)p * ((size_t)K * N * 4));
    for (int u = tid; u < NT * 32; u += 256) {
        int nt = u >> 5, lane = u & 31;
        int n = nt * 8 + (lane >> 2), q = (lane & 3) * 2;
        uint32_t hp[2], lp[2];
#pragma unroll
        for (int r = 0; r < 2; r++) {
            float w0 = tile[(q + 8 * r) * N + n];
            float w1 = tile[(q + 8 * r + 1) * N + n];
            split_pack_f16(w0, w1, hp[r], lp[r]);
        }
        uint4 v; v.x = hp[0]; v.y = hp[1]; v.z = lp[0]; v.w = lp[1];
        dst[((size_t)kt * NT + nt) * 32 + lane] = v;
    }
}

__global__ void prep_all_kernel(const float* __restrict__ W1, const float* __restrict__ W2,
                                const float* __restrict__ W3, const float* __restrict__ W4)
{
    __shared__ float tile[16 * HIDD];
    switch (blockIdx.z) {
        case 0: prep_dev<HIDD, OBSD>(W1, OFF_L1, tile); break;
        case 1: prep_dev<HIDD, HIDD>(W2, OFF_L2, tile); break;
        case 2: prep_dev<HIDD, HIDD>(W3, OFF_L3, tile); break;
        default: prep_dev<ACTD, HIDD>(W4, OFF_L4, tile); break;
    }
}

// ---------------- fused main kernel ----------------
// Per-WG A-fragment layout (m in [0,64)): idx(m,k) -> uint32 slot
//   mtile=m/16, ktile=k/16, a_lane=(m%8)*4+((k%8)/2), r=2*((k%16)>=8)+((m%16)>=8)
//   idx = ((mtile*16 + ktile)*32 + a_lane)*4 + r
// Within a WG: 8 warps, warp wn owns cols [wn*32, +32), all 4 mtiles.
// 2-term MMA: D = Ah*Whi + Ah*Wlo.

template<int K, bool ACT, int NEXTN>
__device__ __forceinline__ void hidden_layer(
    uint32_t* ah, float* red1, float* red2,
    const uint4* __restrict__ bfr,
    const float* __restrict__ nb, const float* __restrict__ ng, const float* __restrict__ nbe,
    const float* parC, float* parN, int wtid, int barid, volatile int* sig)
{
    const int lane = wtid & 31;
    const int wn   = wtid >> 5;
    const uint4* ah4 = reinterpret_cast<const uint4*>(ah);

    float acc[4][4][4];
#pragma unroll
    for (int q = 0; q < 4; q++)
#pragma unroll
        for (int nt = 0; nt < 4; nt++)
#pragma unroll
            for (int r = 0; r < 4; r++) acc[q][nt][r] = 0.f;

    const uint4* bwarp = bfr + (size_t)wn * 128 + lane;   // + kt*1024 + nt*32
    constexpr int KTN = K / 16;

    uint4 B[4];
#pragma unroll
    for (int nt = 0; nt < 4; nt++)
        B[nt] = __ldg(bwarp + nt * 32);

#pragma unroll 1
    for (int kt = 0; kt < KTN; kt++) {
        uint4 Bn[4];
        if (kt + 1 < KTN) {
#pragma unroll
            for (int nt = 0; nt < 4; nt++)
                Bn[nt] = __ldg(bwarp + (size_t)(kt + 1) * 1024 + nt * 32);
        }
#pragma unroll
        for (int q = 0; q < 4; q++) {
            uint4 Ah = ah4[(q * 16 + kt) * 32 + lane];
#pragma unroll
            for (int nt = 0; nt < 4; nt++) {
                mma16816(acc[q][nt], Ah, B[nt].x, B[nt].y);  // A * W_hi
                mma16816(acc[q][nt], Ah, B[nt].z, B[nt].w);  // A * W_lo
            }
        }
#pragma unroll
        for (int nt = 0; nt < 4; nt++) B[nt] = Bn[nt];
    }

    // anti-phase stagger signal (timing only, no data dependence)
    if (sig && wtid == 0) *sig = 1;

    // stage NEXT layer's params (overlaps epilogue)
    for (int i = wtid; i < 3 * NEXTN; i += 256)
        parN[i] = (i < NEXTN) ? nb[i] : (i < 2 * NEXTN ? ng[i - NEXTN] : nbe[i - 2 * NEXTN]);

    // P1: bias + per-row partial sums (bias hoisted)
    const int nbase = wn * 32 + (lane & 3) * 2;
    float2 bb[4];
#pragma unroll
    for (int nt = 0; nt < 4; nt++)
        bb[nt] = *reinterpret_cast<const float2*>(parC + nbase + nt * 8);

#pragma unroll
    for (int q = 0; q < 4; q++) {
        float s1a = 0.f, s2a = 0.f, s1b = 0.f, s2b = 0.f;
#pragma unroll
        for (int nt = 0; nt < 4; nt++) {
            float y0 = acc[q][nt][0] + bb[nt].x, y1 = acc[q][nt][1] + bb[nt].y;
            float y2 = acc[q][nt][2] + bb[nt].x, y3 = acc[q][nt][3] + bb[nt].y;
            acc[q][nt][0] = y0; acc[q][nt][1] = y1;
            acc[q][nt][2] = y2; acc[q][nt][3] = y3;
            s1a += y0 + y1; s2a = fmaf(y0, y0, fmaf(y1, y1, s2a));
            s1b += y2 + y3; s2b = fmaf(y2, y2, fmaf(y3, y3, s2b));
        }
        s1a += __shfl_xor_sync(~0u, s1a, 1); s1a += __shfl_xor_sync(~0u, s1a, 2);
        s2a += __shfl_xor_sync(~0u, s2a, 1); s2a += __shfl_xor_sync(~0u, s2a, 2);
        s1b += __shfl_xor_sync(~0u, s1b, 1); s1b += __shfl_xor_sync(~0u, s1b, 2);
        s2b += __shfl_xor_sync(~0u, s2b, 1); s2b += __shfl_xor_sync(~0u, s2b, 2);
        if ((lane & 3) == 0) {
            int m0 = q * 16 + (lane >> 2);
            red1[wn * 64 + m0]     = s1a; red2[wn * 64 + m0]     = s2a;
            red1[wn * 64 + m0 + 8] = s1b; red2[wn * 64 + m0 + 8] = s2b;
        }
    }
    BARWG(barid);
    if (wtid < 64) {
        float t1 = 0.f, t2 = 0.f;
#pragma unroll
        for (int w = 0; w < 8; w++) { t1 += red1[w * 64 + wtid]; t2 += red2[w * 64 + wtid]; }
        float mean = t1 * (1.f / 256.f);
        float var  = fmaf(-mean, mean, t2 * (1.f / 256.f));
        float rstd = rsqrtf(var + EPSV);
        red1[wtid] = mean; red2[wtid] = rstd;
    }
    BARWG(barid);

    // P3: normalize + activation + write next layer's A (fp16 hi only)
    float2 gg[4], ee[4];
#pragma unroll
    for (int nt = 0; nt < 4; nt++) {
        gg[nt] = *reinterpret_cast<const float2*>(parC + 256 + nbase + nt * 8);
        ee[nt] = *reinterpret_cast<const float2*>(parC + 512 + nbase + nt * 8);
    }
#pragma unroll
    for (int q = 0; q < 4; q++) {
        int mA = q * 16 + (lane >> 2);
        float meanA = red1[mA],     rstdA = red2[mA];
        float meanB = red1[mA + 8], rstdB = red2[mA + 8];
#pragma unroll
        for (int nt = 0; nt < 4; nt++) {
            int n0 = nbase + nt * 8;
            float y0 = fmaf((acc[q][nt][0] - meanA) * rstdA, gg[nt].x, ee[nt].x);
            float y1 = fmaf((acc[q][nt][1] - meanA) * rstdA, gg[nt].y, ee[nt].y);
            float y2 = fmaf((acc[q][nt][2] - meanB) * rstdB, gg[nt].x, ee[nt].x);
            float y3 = fmaf((acc[q][nt][3] - meanB) * rstdB, gg[nt].y, ee[nt].y);
            if (ACT) { y0 = elu1(y0); y1 = elu1(y1); y2 = elu1(y2); y3 = elu1(y3); }
            int aln = ((lane >> 2) << 2) + ((n0 & 7) >> 1);
            int rA  = ((n0 & 15) >= 8) ? 2 : 0;
            int idxb = ((q * 16 + (n0 >> 4)) * 32 + aln) * 4 + rA;
            *reinterpret_cast<uint2*>(ah + idxb) =
                make_uint2(pack_f16(y0, y1), pack_f16(y2, y3));
        }
    }
    BARWG(barid);
}

// final layer: K=256, N=32, 64 rows per WG. Split-K across WG warp halves.
__device__ __forceinline__ void final_layer(
    uint32_t* ah, const uint4* __restrict__ bfr,
    const float* parC, float* __restrict__ out, int r0, int p, int wtid, int barid)
{
    const int lane = wtid & 31, wwid = wtid >> 5;
    const int m = wwid & 3, kh = wwid >> 2;
    const uint4* ah4 = reinterpret_cast<const uint4*>(ah);
    float* scr = reinterpret_cast<float*>(ah);         // WG-private A region reused

    float acc[4][4];
#pragma unroll
    for (int nt = 0; nt < 4; nt++)
#pragma unroll
        for (int r = 0; r < 4; r++) acc[nt][r] = 0.f;

#pragma unroll 1
    for (int k = 0; k < 8; k++) {
        const int kt = kh * 8 + k;
        uint4 B[4];
#pragma unroll
        for (int nt = 0; nt < 4; nt++)
            B[nt] = __ldg(&bfr[((size_t)kt * 4 + nt) * 32 + lane]);
        uint4 Ah = ah4[(m * 16 + kt) * 32 + lane];
#pragma unroll
        for (int nt = 0; nt < 4; nt++) {
            mma16816(acc[nt], Ah, B[nt].x, B[nt].y);
            mma16816(acc[nt], Ah, B[nt].z, B[nt].w);
        }
    }
    BARWG(barid);        // all A reads done; scr reusable
    if (kh == 1) {
        float4* s4 = reinterpret_cast<float4*>(scr) + (m * 32 + lane) * 4;
#pragma unroll
        for (int nt = 0; nt < 4; nt++)
            s4[nt] = make_float4(acc[nt][0], acc[nt][1], acc[nt][2], acc[nt][3]);
    }
    BARWG(barid);
    if (kh == 1) return;

    const float4* s4 = reinterpret_cast<const float4*>(scr) + (m * 32 + lane) * 4;
#pragma unroll
    for (int nt = 0; nt < 4; nt++) {
        float4 v = s4[nt];
        acc[nt][0] += v.x; acc[nt][1] += v.y; acc[nt][2] += v.z; acc[nt][3] += v.w;
    }

    const int nbase = (lane & 3) * 2;
    float s1a = 0.f, s2a = 0.f, s1b = 0.f, s2b = 0.f;
#pragma unroll
    for (int nt = 0; nt < 4; nt++) {
        float2 b2 = *reinterpret_cast<const float2*>(parC + nbase + nt * 8);
        float y0 = acc[nt][0] + b2.x, y1 = acc[nt][1] + b2.y;
        float y2 = acc[nt][2] + b2.x, y3 = acc[nt][3] + b2.y;
        acc[nt][0] = y0; acc[nt][1] = y1; acc[nt][2] = y2; acc[nt][3] = y3;
        s1a += y0 + y1; s2a = fmaf(y0, y0, fmaf(y1, y1, s2a));
        s1b += y2 + y3; s2b = fmaf(y2, y2, fmaf(y3, y3, s2b));
    }
    s1a += __shfl_xor_sync(~0u, s1a, 1); s1a += __shfl_xor_sync(~0u, s1a, 2);
    s2a += __shfl_xor_sync(~0u, s2a, 1); s2a += __shfl_xor_sync(~0u, s2a, 2);
    s1b += __shfl_xor_sync(~0u, s1b, 1); s1b += __shfl_xor_sync(~0u, s1b, 2);
    s2b += __shfl_xor_sync(~0u, s2b, 1); s2b += __shfl_xor_sync(~0u, s2b, 2);
    const float meanA = s1a * (1.f / 32.f);
    const float rstdA = rsqrtf(fmaf(-meanA, meanA, s2a * (1.f / 32.f)) + EPSV);
    const float meanB = s1b * (1.f / 32.f);
    const float rstdB = rsqrtf(fmaf(-meanB, meanB, s2b * (1.f / 32.f)) + EPSV);

    const int mA = m * 16 + (lane >> 2);
#pragma unroll
    for (int nt = 0; nt < 4; nt++) {
        int n0 = nbase + nt * 8;
        float2 g2 = *reinterpret_cast<const float2*>(parC + 32 + n0);
        float2 e2 = *reinterpret_cast<const float2*>(parC + 64 + n0);
        float2 o;
        o.x = fmaf((acc[nt][0] - meanA) * rstdA, g2.x, e2.x);
        o.y = fmaf((acc[nt][1] - meanA) * rstdA, g2.y, e2.y);
        *reinterpret_cast<float2*>(out + (size_t)(r0 + mA) * (NP * ACTD) + p * ACTD + n0) = o;
        o.x = fmaf((acc[nt][2] - meanB) * rstdB, g2.x, e2.x);
        o.y = fmaf((acc[nt][3] - meanB) * rstdB, g2.y, e2.y);
        *reinterpret_cast<float2*>(out + (size_t)(r0 + mA + 8) * (NP * ACTD) + p * ACTD + n0) = o;
    }
}

__global__ __launch_bounds__(512, 1)
void mlp_fused_kernel(
    const float* __restrict__ obs,
    const float* __restrict__ b1, const float* __restrict__ g1, const float* __restrict__ be1,
    const float* __restrict__ b2, const float* __restrict__ g2, const float* __restrict__ be2,
    const float* __restrict__ b3, const float* __restrict__ g3, const float* __restrict__ be3,
    const float* __restrict__ b4, const float* __restrict__ g4, const float* __restrict__ be4,
    float* __restrict__ out)
{
    extern __shared__ unsigned char smem[];
    const int tid  = threadIdx.x;
    const int wg   = tid >> 8;           // warpgroup 0 or 1
    const int wtid = tid & 255;
    const int barid = 1 + wg;
    const int p   = blockIdx.y;
    const int r0  = blockIdx.x * MT + wg * 64;

    uint32_t* ah  = reinterpret_cast<uint32_t*>(smem + A_OFF(wg));
    float* par0   = reinterpret_cast<float*>(smem + PAR_OFF(wg));
    float* par1   = par0 + 768;
    float* red1   = reinterpret_cast<float*>(smem + RED_OFF(wg));
    float* red2   = red1 + 512;
    volatile int* flag = reinterpret_cast<volatile int*>(smem + FLAG_OFF);

    if (tid == 0) *flag = 0;

    // stage observation tile (this WG's 64 rows) as fp16 A-frags + layer-1 params
    {
        const int m = wtid >> 2, q4 = wtid & 3;
        const float* orow = obs + (size_t)(r0 + m) * OBSD + q4 * 32;
#pragma unroll
        for (int j = 0; j < 16; j++) {
            float2 v = reinterpret_cast<const float2*>(orow)[j];
            int k = q4 * 32 + j * 2;
            int aln = ((m & 7) << 2) + ((k & 7) >> 1);
            int r = (((k & 15) >= 8) ? 2 : 0) + (((m & 15) >= 8) ? 1 : 0);
            int idx = (((m >> 4) * 16 + (k >> 4)) * 32 + aln) * 4 + r;
            ah[idx] = pack_f16(v.x, v.y);
        }
        const float* s1 = b1 + p * HIDD;
        const float* s2 = g1 + p * HIDD;
        const float* s3 = be1 + p * HIDD;
        for (int i = wtid; i < 768; i += 256)
            par0[i] = (i < 256) ? s1[i] : (i < 512 ? s2[i - 256] : s3[i - 512]);
    }
    __syncthreads();    // publishes flag=0 + all staging (full CTA, before WG divergence)

    // anti-phase stagger: WG1 waits until WG0 finishes its layer-1 MMA loop
    if (wg == 1) {
        while (*flag == 0) __nanosleep(32);
    }

    hidden_layer<OBSD, true, HIDD>(ah, red1, red2,
        reinterpret_cast<const uint4*>(g_wimg + OFF_L1 + (size_t)p * L1_BYTES),
        b2 + p * HIDD, g2 + p * HIDD, be2 + p * HIDD, par0, par1, wtid, barid,
        (wg == 0) ? flag : nullptr);
    hidden_layer<HIDD, true, HIDD>(ah, red1, red2,
        reinterpret_cast<const uint4*>(g_wimg + OFF_L2 + (size_t)p * L2_BYTES),
        b3 + p * HIDD, g3 + p * HIDD, be3 + p * HIDD, par1, par0, wtid, barid, nullptr);
    hidden_layer<HIDD, true, ACTD>(ah, red1, red2,
        reinterpret_cast<const uint4*>(g_wimg + OFF_L3 + (size_t)p * L2_BYTES),
        b4 + p * ACTD, g4 + p * ACTD, be4 + p * ACTD, par0, par1, wtid, barid, nullptr);
    final_layer(ah,
        reinterpret_cast<const uint4*>(g_wimg + OFF_L4 + (size_t)p * L4_BYTES),
        par1, out, r0, p, wtid, barid);
}

// ---------------- launch ----------------
extern "C" void kernel_launch(void* const* d_in, const int* in_sizes, int n_in,
                              void* d_out, int out_size)
{
    const float* obs = (const float*)d_in[0];
    const float* W1  = (const float*)d_in[1];
    const float* b1  = (const float*)d_in[2];
    const float* g1  = (const float*)d_in[3];
    const float* be1 = (const float*)d_in[4];
    const float* W2  = (const float*)d_in[5];
    const float* b2  = (const float*)d_in[6];
    const float* g2  = (const float*)d_in[7];
    const float* be2 = (const float*)d_in[8];
    const float* W3  = (const float*)d_in[9];
    const float* b3  = (const float*)d_in[10];
    const float* g3  = (const float*)d_in[11];
    const float* be3 = (const float*)d_in[12];
    const float* W4  = (const float*)d_in[13];
    const float* b4  = (const float*)d_in[14];
    const float* g4  = (const float*)d_in[15];
    const float* be4 = (const float*)d_in[16];
    float* out = (float*)d_out;

    prep_all_kernel<<<dim3(NP, HIDD / 16, 4), 256>>>(W1, W2, W3, W4);

    cudaFuncSetAttribute(mlp_fused_kernel,
                         cudaFuncAttributeMaxDynamicSharedMemorySize, DSMEM_BYTES);
    dim3 grid(NB / MT, NP);
    mlp_fused_kernel<<<grid, 512, DSMEM_BYTES>>>(
        obs, b1, g1, be1, b2, g2, be2, b3, g3, be3, b4, g4, be4, out);
}